// round 3
// baseline (speedup 1.0000x reference)
#include <cuda_runtime.h>
#include <math.h>
#include <float.h>

// ---------------- problem constants ----------------
#define DIM 1024
constexpr int B_ = 8, S_ = 512, L_ = 4;
constexpr int M_ = B_ * S_;          // 4096 rows
constexpr int V_ = 32000;
constexpr int STEPS = 8;
constexpr float LR = 0.1f;

constexpr int NROWS  = B_ * (S_ - 1); // 4088 CE rows
constexpr int NSPLIT = 10;            // vocab splits (32000/10 = 3200 = 25*128)
constexpr int VSPLIT = V_ / NSPLIT;
constexpr int NPCB = 256;             // pc-loss partial blocks
constexpr int NCEB = 16;              // ce partial blocks

// ---------------- device scratch (allocation-free rule) ----------------
__device__ float g_x[M_ * DIM];                 // 16 MB embedded input
__device__ float g_states[L_ * M_ * DIM];       // 64 MB
__device__ float g_eps[L_ * M_ * DIM];          // 64 MB
__device__ float g_pm[NROWS * NSPLIT];
__device__ float g_ps[NROWS * NSPLIT];
__device__ float g_pt[NROWS * NSPLIT];
__device__ double g_pc_part[NPCB];
__device__ double g_ce_part[NCEB];

// ---------------- embedding gather: x = emb[input_ids] ----------------
__global__ void gather_kernel(const int* __restrict__ ids,
                              const float* __restrict__ emb) {
    int row = blockIdx.x;                       // 4096
    int id  = ids[row];
    const float4* src = reinterpret_cast<const float4*>(emb + (size_t)id * DIM);
    float4* dst = reinterpret_cast<float4*>(g_x + (size_t)row * DIM);
    dst[threadIdx.x] = src[threadIdx.x];        // 256 threads * float4 = 1024 floats
}

// ---------------- states <- states_init ----------------
__global__ void copy_states_kernel(const float* __restrict__ si) {
    int idx = blockIdx.x * blockDim.x + threadIdx.x;   // over L*M*DIM/4 float4
    reinterpret_cast<float4*>(g_states)[idx] =
        reinterpret_cast<const float4*>(si)[idx];
}

// ---------------- fused SGEMM ----------------
// MODE 0 (eps):    eps_k = mu_k - states_k @ W_k^T - b_k        (NT gemm)
// MODE 1 (update): states_k += 0.1*(eps_k @ W_k) - 0.1*eps_{k+1} (NN gemm)
template<int MODE>
__global__ __launch_bounds__(256, 2)
void gemm_kernel(int k, const float* __restrict__ Wst, const float* __restrict__ bst) {
    constexpr int BM = 128, BN = 128, BK = 16;
    __shared__ float As[BK][BM];
    __shared__ float Bs[BK][BN];

    const int t  = threadIdx.x;
    const int m0 = blockIdx.y * BM;
    const int n0 = blockIdx.x * BN;
    const int tx = t & 15, ty = t >> 4;

    const float* A  = (MODE == 0) ? (g_states + k * (M_ * DIM))
                                  : (g_eps    + k * (M_ * DIM));
    const float* Bp = Wst + k * (DIM * DIM);

    float acc[8][8];
    #pragma unroll
    for (int i = 0; i < 8; i++)
        #pragma unroll
        for (int j = 0; j < 8; j++) acc[i][j] = 0.f;

    for (int k0 = 0; k0 < DIM; k0 += BK) {
        // A tile: 128 rows x 16 k, K-contiguous
        #pragma unroll
        for (int rep = 0; rep < 2; rep++) {
            int idx = t + rep * 256;
            int row = idx >> 2, kq = (idx & 3) << 2;
            float4 v = *reinterpret_cast<const float4*>(&A[(m0 + row) * DIM + k0 + kq]);
            As[kq + 0][row] = v.x; As[kq + 1][row] = v.y;
            As[kq + 2][row] = v.z; As[kq + 3][row] = v.w;
        }
        if (MODE == 0) {
            // NT: Bs[kk][n] = W[(n0+n)*DIM + k0+kk]
            #pragma unroll
            for (int rep = 0; rep < 2; rep++) {
                int idx = t + rep * 256;
                int row = idx >> 2, kq = (idx & 3) << 2;
                float4 v = *reinterpret_cast<const float4*>(&Bp[(n0 + row) * DIM + k0 + kq]);
                Bs[kq + 0][row] = v.x; Bs[kq + 1][row] = v.y;
                Bs[kq + 2][row] = v.z; Bs[kq + 3][row] = v.w;
            }
        } else {
            // NN: Bs[kk][n] = W[(k0+kk)*DIM + n0+n]
            #pragma unroll
            for (int rep = 0; rep < 2; rep++) {
                int idx = t + rep * 256;
                int kr = idx >> 5, nq = (idx & 31) << 2;
                float4 v = *reinterpret_cast<const float4*>(&Bp[(k0 + kr) * DIM + n0 + nq]);
                *reinterpret_cast<float4*>(&Bs[kr][nq]) = v;
            }
        }
        __syncthreads();
        #pragma unroll
        for (int kk = 0; kk < BK; kk++) {
            float a[8], b[8];
            *reinterpret_cast<float4*>(&a[0]) = *reinterpret_cast<const float4*>(&As[kk][ty * 8]);
            *reinterpret_cast<float4*>(&a[4]) = *reinterpret_cast<const float4*>(&As[kk][ty * 8 + 4]);
            *reinterpret_cast<float4*>(&b[0]) = *reinterpret_cast<const float4*>(&Bs[kk][tx * 8]);
            *reinterpret_cast<float4*>(&b[4]) = *reinterpret_cast<const float4*>(&Bs[kk][tx * 8 + 4]);
            #pragma unroll
            for (int i = 0; i < 8; i++)
                #pragma unroll
                for (int j = 0; j < 8; j++) acc[i][j] += a[i] * b[j];
        }
        __syncthreads();
    }

    if (MODE == 0) {
        const float* mu   = (k == 0) ? g_x : g_states + (k - 1) * (M_ * DIM);
        const float* bias = bst + k * DIM;
        float* out = g_eps + k * (M_ * DIM);
        #pragma unroll
        for (int i = 0; i < 8; i++) {
            int m = m0 + ty * 8 + i;
            #pragma unroll
            for (int jq = 0; jq < 8; jq += 4) {
                int n = n0 + tx * 8 + jq;
                float4 mv = *reinterpret_cast<const float4*>(&mu[m * DIM + n]);
                float4 bv = *reinterpret_cast<const float4*>(&bias[n]);
                float4 o;
                o.x = mv.x - acc[i][jq + 0] - bv.x;
                o.y = mv.y - acc[i][jq + 1] - bv.y;
                o.z = mv.z - acc[i][jq + 2] - bv.z;
                o.w = mv.w - acc[i][jq + 3] - bv.w;
                *reinterpret_cast<float4*>(&out[m * DIM + n]) = o;
            }
        }
    } else {
        float* out = g_states + k * (M_ * DIM);
        const bool has_en = (k < L_ - 1);
        const float* en = g_eps + (k + 1) * (M_ * DIM);
        #pragma unroll
        for (int i = 0; i < 8; i++) {
            int m = m0 + ty * 8 + i;
            #pragma unroll
            for (int jq = 0; jq < 8; jq += 4) {
                int n = n0 + tx * 8 + jq;
                float4 sv = *reinterpret_cast<const float4*>(&out[m * DIM + n]);
                float4 ev = has_en ? *reinterpret_cast<const float4*>(&en[m * DIM + n])
                                   : make_float4(0.f, 0.f, 0.f, 0.f);
                float4 o;
                o.x = sv.x + LR * acc[i][jq + 0] - LR * ev.x;
                o.y = sv.y + LR * acc[i][jq + 1] - LR * ev.y;
                o.z = sv.z + LR * acc[i][jq + 2] - LR * ev.z;
                o.w = sv.w + LR * acc[i][jq + 3] - LR * ev.w;
                *reinterpret_cast<float4*>(&out[m * DIM + n]) = o;
            }
        }
    }
}

// ---------------- pc loss: sum of squares over all eps ----------------
__global__ void pc_reduce_kernel() {
    __shared__ double sm[256];
    const int total4 = (L_ * M_ * DIM) / 4;
    double local = 0.0;
    const float4* e4 = reinterpret_cast<const float4*>(g_eps);
    for (int i = blockIdx.x * blockDim.x + threadIdx.x; i < total4;
         i += gridDim.x * blockDim.x) {
        float4 v = e4[i];
        local += (double)v.x * v.x + (double)v.y * v.y +
                 (double)v.z * v.z + (double)v.w * v.w;
    }
    sm[threadIdx.x] = local;
    __syncthreads();
    for (int s = 128; s > 0; s >>= 1) {
        if (threadIdx.x < s) sm[threadIdx.x] += sm[threadIdx.x + s];
        __syncthreads();
    }
    if (threadIdx.x == 0) g_pc_part[blockIdx.x] = sm[0];
}

// ---------------- CE: fused logits GEMM + online softmax ----------------
// grid (NSPLIT, ceil(NROWS/64)); per block: 64 rows x its 3200-vocab split.
__global__ __launch_bounds__(256, 2)
void ce_main_kernel(const int* __restrict__ targets,
                    const float* __restrict__ outW,
                    const float* __restrict__ outB) {
    constexpr int CM = 64, CN = 128, CK = 16;
    __shared__ float As[CK][CM];
    __shared__ float Ws[CK][CN];
    __shared__ int rowoff[CM];
    __shared__ int rowtgt[CM];

    const int split = blockIdx.x;
    const int m0 = blockIdx.y * CM;
    const int t = threadIdx.x;
    const int tx = t & 15, ty = t >> 4;

    if (t < CM) {
        int rg = m0 + t;
        if (rg < NROWS) {
            int b = rg / (S_ - 1), s = rg % (S_ - 1);
            rowoff[t] = (b * S_ + s) * DIM;
            rowtgt[t] = targets[b * S_ + s + 1];
        } else { rowoff[t] = 0; rowtgt[t] = -1; }  // safe in-bounds dummy row
    }
    __syncthreads();

    const float* S3 = g_states + (L_ - 1) * (M_ * DIM);

    float runm[4], runs[4], runt[4];
    #pragma unroll
    for (int i = 0; i < 4; i++) { runm[i] = -1e30f; runs[i] = 0.f; runt[i] = -1e30f; }

    for (int vt = 0; vt < VSPLIT / CN; vt++) {
        const int n0 = split * VSPLIT + vt * CN;
        float acc[4][8];
        #pragma unroll
        for (int i = 0; i < 4; i++)
            #pragma unroll
            for (int j = 0; j < 8; j++) acc[i][j] = 0.f;

        for (int k0 = 0; k0 < DIM; k0 += CK) {
            { // A: 64 rows x 16 k -> 256 float4, one per thread
                int row = t >> 2, kq = (t & 3) << 2;
                int ro = rowoff[row];
                float4 v = *reinterpret_cast<const float4*>(&S3[ro + k0 + kq]);
                As[kq + 0][row] = v.x; As[kq + 1][row] = v.y;
                As[kq + 2][row] = v.z; As[kq + 3][row] = v.w;
            }
            #pragma unroll
            for (int rep = 0; rep < 2; rep++) { // W: 128 vocab x 16 k
                int idx = t + rep * 256;
                int vr = idx >> 2, kq = (idx & 3) << 2;
                float4 v = *reinterpret_cast<const float4*>(&outW[(n0 + vr) * DIM + k0 + kq]);
                Ws[kq + 0][vr] = v.x; Ws[kq + 1][vr] = v.y;
                Ws[kq + 2][vr] = v.z; Ws[kq + 3][vr] = v.w;
            }
            __syncthreads();
            #pragma unroll
            for (int kk = 0; kk < CK; kk++) {
                float a[4], b[8];
                *reinterpret_cast<float4*>(&a[0]) = *reinterpret_cast<const float4*>(&As[kk][ty * 4]);
                *reinterpret_cast<float4*>(&b[0]) = *reinterpret_cast<const float4*>(&Ws[kk][tx * 8]);
                *reinterpret_cast<float4*>(&b[4]) = *reinterpret_cast<const float4*>(&Ws[kk][tx * 8 + 4]);
                #pragma unroll
                for (int i = 0; i < 4; i++)
                    #pragma unroll
                    for (int j = 0; j < 8; j++) acc[i][j] += a[i] * b[j];
            }
            __syncthreads();
        }

        // online softmax update (dummy rows have rowtgt == -1; they update
        // local state but never write out, so correctness is unaffected)
        #pragma unroll
        for (int i = 0; i < 4; i++) {
            float l[8], tmax = -1e30f;
            #pragma unroll
            for (int j = 0; j < 8; j++) {
                l[j] = acc[i][j] + outB[n0 + tx * 8 + j];
                tmax = fmaxf(tmax, l[j]);
            }
            float nm = fmaxf(runm[i], tmax);
            float add = 0.f;
            #pragma unroll
            for (int j = 0; j < 8; j++) add += __expf(l[j] - nm);
            runs[i] = runs[i] * __expf(runm[i] - nm) + add;
            runm[i] = nm;
            int tg = rowtgt[ty * 4 + i];
            #pragma unroll
            for (int j = 0; j < 8; j++)
                if (n0 + tx * 8 + j == tg) runt[i] = l[j];
        }
    }

    // reduce across the 16 tx lanes (xor stays within 16-lane halves of a warp)
    #pragma unroll
    for (int i = 0; i < 4; i++) {
        float m = runm[i], sv = runs[i], tv = runt[i];
        #pragma unroll
        for (int off = 8; off >= 1; off >>= 1) {
            float om = __shfl_xor_sync(0xffffffff, m, off);
            float os = __shfl_xor_sync(0xffffffff, sv, off);
            float ot = __shfl_xor_sync(0xffffffff, tv, off);
            float nm = fmaxf(m, om);
            sv = sv * __expf(m - nm) + os * __expf(om - nm);
            m = nm;
            tv = fmaxf(tv, ot);
        }
        if (tx == 0) {
            int rg = m0 + ty * 4 + i;
            if (rg < NROWS) {
                g_pm[rg * NSPLIT + split] = m;
                g_ps[rg * NSPLIT + split] = sv;
                g_pt[rg * NSPLIT + split] = tv;
            }
        }
    }
}

__global__ void ce_combine_kernel() {
    __shared__ double sm[256];
    double local = 0.0;
    for (int r = blockIdx.x * blockDim.x + threadIdx.x; r < NROWS;
         r += gridDim.x * blockDim.x) {
        float M = -1e30f;
        #pragma unroll
        for (int sp = 0; sp < NSPLIT; sp++) M = fmaxf(M, g_pm[r * NSPLIT + sp]);
        float Z = 0.f;
        #pragma unroll
        for (int sp = 0; sp < NSPLIT; sp++)
            Z += g_ps[r * NSPLIT + sp] * __expf(g_pm[r * NSPLIT + sp] - M);
        float tl = -1e30f;
        #pragma unroll
        for (int sp = 0; sp < NSPLIT; sp++) tl = fmaxf(tl, g_pt[r * NSPLIT + sp]);
        local += (double)M + log((double)Z) - (double)tl;
    }
    sm[threadIdx.x] = local;
    __syncthreads();
    for (int s = 128; s > 0; s >>= 1) {
        if (threadIdx.x < s) sm[threadIdx.x] += sm[threadIdx.x + s];
        __syncthreads();
    }
    if (threadIdx.x == 0) g_ce_part[blockIdx.x] = sm[0];
}

__global__ void finalize_kernel(float* out) {
    double pc = 0.0, ce = 0.0;
    for (int i = 0; i < NPCB; i++) pc += g_pc_part[i];
    for (int i = 0; i < NCEB; i++) ce += g_ce_part[i];
    out[0] = (float)(ce / (double)NROWS);
    out[1] = (float)(pc / ((double)L_ * M_ * DIM));
}

// ---------------- launch ----------------
extern "C" void kernel_launch(void* const* d_in, const int* in_sizes, int n_in,
                              void* d_out, int out_size) {
    const int*   input_ids   = (const int*)d_in[0];
    const int*   targets     = (const int*)d_in[1];
    const float* emb         = (const float*)d_in[2];
    const float* W_stack     = (const float*)d_in[3];
    const float* b_stack     = (const float*)d_in[4];
    const float* out_W       = (const float*)d_in[5];
    const float* out_b       = (const float*)d_in[6];
    const float* states_init = (const float*)d_in[7];
    float* out = (float*)d_out;

    // init scratch
    copy_states_kernel<<<(L_ * M_ * DIM / 4 + 255) / 256, 256>>>(states_init);
    gather_kernel<<<M_, 256>>>(input_ids, emb);

    dim3 ggrid(DIM / 128, M_ / 128); // (8, 32)
    for (int step = 0; step < STEPS; step++) {
        for (int k = 0; k < L_; k++)
            gemm_kernel<0><<<ggrid, 256>>>(k, W_stack, b_stack);
        for (int k = 0; k < L_; k++)
            gemm_kernel<1><<<ggrid, 256>>>(k, W_stack, b_stack);
    }
    // final eps for pc loss
    for (int k = 0; k < L_; k++)
        gemm_kernel<0><<<ggrid, 256>>>(k, W_stack, b_stack);

    pc_reduce_kernel<<<NPCB, 256>>>();

    dim3 cegrid(NSPLIT, (NROWS + 63) / 64); // (10, 64)
    ce_main_kernel<<<cegrid, 256>>>(targets, out_W, out_b);
    ce_combine_kernel<<<NCEB, 256>>>();
    finalize_kernel<<<1, 1>>>(out);
}

// round 5
// speedup vs baseline: 3.2083x; 3.2083x over previous
#include <cuda_runtime.h>
#include <cuda_bf16.h>
#include <math.h>
#include <stdint.h>

#define DIM 1024
constexpr int B_ = 8, S_ = 512, L_ = 4;
constexpr int M_ = B_ * S_;
constexpr int V_ = 32000;
constexpr int STEPS = 8;
constexpr float LR = 0.1f;
constexpr int MD = M_ * DIM, LMD = L_ * MD;
constexpr int NROWS = B_ * (S_ - 1);
constexpr int NSP = V_ / 128;     // 250
constexpr int NPCB = 256, NCEB = 16;

__device__ float g_x[MD];
__device__ float g_states[LMD];
__device__ float g_eps[LMD];
__device__ __nv_bfloat16 g_sh[LMD], g_sl[LMD], g_eh[LMD], g_el[LMD];
__device__ __nv_bfloat16 g_Wh[L_*DIM*DIM], g_Wl[L_*DIM*DIM];
__device__ __nv_bfloat16 g_Wth[L_*DIM*DIM], g_Wtl[L_*DIM*DIM];
__device__ __nv_bfloat16 g_oWh[V_*DIM];
__device__ float g_pm[4096*NSP], g_ps[4096*NSP], g_pt[4096*NSP];
__device__ double g_pc_part[NPCB], g_ce_part[NCEB];

// ---- baseline-ISA helpers ----
__device__ __forceinline__ uint32_t smem_u32(const void* p){
    uint32_t a; asm("{ .reg .u64 t; cvta.to.shared.u64 t, %1; cvt.u32.u64 %0, t; }":"=r"(a):"l"(p)); return a;
}
#define CP16(dst, src) \
    asm volatile("cp.async.cg.shared.global [%0], [%1], 16;" \
        :: "r"(dst), "l"(__cvta_generic_to_global(src)) : "memory")
#define CP_COMMIT() asm volatile("cp.async.commit_group;" ::: "memory")
#define CP_WAIT1()  asm volatile("cp.async.wait_group 1;" ::: "memory")
#define CP_WAIT0()  asm volatile("cp.async.wait_group 0;" ::: "memory")
#define LDSM4(r0,r1,r2,r3,addr) \
    asm volatile("ldmatrix.sync.aligned.m8n8.x4.shared.b16 {%0,%1,%2,%3}, [%4];" \
        : "=r"(r0),"=r"(r1),"=r"(r2),"=r"(r3) : "r"(addr))
#define MMA(d, a, b) \
    asm volatile("mma.sync.aligned.m16n8k16.row.col.f32.bf16.bf16.f32 " \
        "{%0,%1,%2,%3},{%4,%5,%6,%7},{%8,%9},{%0,%1,%2,%3};" \
        : "+f"((d)[0]),"+f"((d)[1]),"+f"((d)[2]),"+f"((d)[3]) \
        : "r"((a)[0]),"r"((a)[1]),"r"((a)[2]),"r"((a)[3]),"r"((b)[0]),"r"((b)[1]))

// ---- prep kernels ----
__global__ void gather_kernel(const int* __restrict__ ids, const float* __restrict__ emb){
    int row = blockIdx.x, id = ids[row];
    reinterpret_cast<float4*>(g_x + (size_t)row*DIM)[threadIdx.x] =
        reinterpret_cast<const float4*>(emb + (size_t)id*DIM)[threadIdx.x];
}
__global__ void split_states_kernel(const float* __restrict__ si){
    int i = blockIdx.x*blockDim.x + threadIdx.x;
    float v = si[i];
    g_states[i] = v;
    __nv_bfloat16 h = __float2bfloat16(v);
    g_sh[i] = h; g_sl[i] = __float2bfloat16(v - __bfloat162float(h));
}
__global__ void split_w_kernel(const float* __restrict__ W){
    __shared__ float tile[32][33];
    int l = blockIdx.z, i0 = blockIdx.y*32, j0 = blockIdx.x*32;
    int tx = threadIdx.x, ty = threadIdx.y;
    const float* Wb = W + (size_t)l*DIM*DIM;
    #pragma unroll
    for (int r = 0; r < 4; r++){
        int i = i0 + ty + r*8;
        float w = Wb[(size_t)i*DIM + j0 + tx];
        __nv_bfloat16 h = __float2bfloat16(w);
        size_t o = (size_t)l*DIM*DIM + (size_t)i*DIM + j0 + tx;
        g_Wh[o] = h; g_Wl[o] = __float2bfloat16(w - __bfloat162float(h));
        tile[ty + r*8][tx] = w;
    }
    __syncthreads();
    #pragma unroll
    for (int r = 0; r < 4; r++){
        int jr = ty + r*8;
        float w = tile[tx][jr];
        __nv_bfloat16 h = __float2bfloat16(w);
        size_t o = (size_t)l*DIM*DIM + (size_t)(j0+jr)*DIM + i0 + tx;
        g_Wth[o] = h; g_Wtl[o] = __float2bfloat16(w - __bfloat162float(h));
    }
}
__global__ void split_ow_kernel(const float* __restrict__ oW){
    int i = blockIdx.x*blockDim.x + threadIdx.x;
    g_oWh[i] = __float2bfloat16(oW[i]);
}

// ---- mma.sync step GEMM: block 128x256, BK=32, 8 warps of 64x64 ----
// MODE0: eps_k = mu_k - states_k @ W_k^T - b_k
// MODE1: states_k += LR*(eps_k @ W_k) - LR*eps_{k+1}
// smem stage (61440B): Ah@0 Al@10240 Bh@20480 Bl@40960; rows padded to 80B.
template<int MODE>
__global__ __launch_bounds__(256,1)
void mm_step(int k, const float* __restrict__ bst){
    extern __shared__ char smem[];
    const uint32_t sb = smem_u32(smem);
    const int tid = threadIdx.x;
    const int m0 = blockIdx.y*128, n0 = blockIdx.x*256;
    const __nv_bfloat16* Ah = (MODE==0?g_sh:g_eh) + (size_t)k*MD + (size_t)m0*DIM;
    const __nv_bfloat16* Al = (MODE==0?g_sl:g_el) + (size_t)k*MD + (size_t)m0*DIM;
    const __nv_bfloat16* Bh = (MODE==0?g_Wh:g_Wth) + (size_t)k*DIM*DIM + (size_t)n0*DIM;
    const __nv_bfloat16* Bl = (MODE==0?g_Wl:g_Wtl) + (size_t)k*DIM*DIM + (size_t)n0*DIM;

    auto issue = [&](int kt){
        const uint32_t st = sb + (uint32_t)(kt&1)*61440u;
        const int k0 = kt*32;
        #pragma unroll
        for (int it = 0; it < 2; it++){      // A: 512 chunks
            int c = it*256 + tid, row = c>>2, cc = c&3;
            uint32_t d = st + row*80 + cc*16;
            const __nv_bfloat16* s = Ah + (size_t)row*DIM + k0 + cc*8;
            CP16(d, s);
            CP16(d + 10240, Al + (size_t)row*DIM + k0 + cc*8);
        }
        #pragma unroll
        for (int it = 0; it < 4; it++){      // B: 1024 chunks
            int c = it*256 + tid, row = c>>2, cc = c&3;
            uint32_t d = st + 20480 + row*80 + cc*16;
            CP16(d, Bh + (size_t)row*DIM + k0 + cc*8);
            CP16(d + 20480, Bl + (size_t)row*DIM + k0 + cc*8);
        }
        CP_COMMIT();
    };

    const int w = tid>>5, l = tid&31;
    const int wm = w>>2, wn = w&3;
    const int aoff = wm*64, boff = wn*64;
    const uint32_t apart = (uint32_t)((aoff + ((l>>3)&1)*8 + (l&7))*80 + (l>>4)*16);
    const uint32_t bpart = (uint32_t)((boff + (l>>4)*8 + (l&7))*80 + ((l>>3)&1)*16);

    float acc[4][8][4];
    #pragma unroll
    for (int i=0;i<4;i++)
        #pragma unroll
        for (int j=0;j<8;j++)
            #pragma unroll
            for (int q=0;q<4;q++) acc[i][j][q] = 0.f;

    issue(0); issue(1);
    for (int kt = 0; kt < 32; kt++){
        if (kt == 31) CP_WAIT0(); else CP_WAIT1();
        __syncthreads();
        const uint32_t st = sb + (uint32_t)(kt&1)*61440u;
        #pragma unroll
        for (int ks = 0; ks < 2; ks++){
            uint32_t ah[4][4], al[4][4], bh[8][2], bl[8][2];
            #pragma unroll
            for (int i=0;i<4;i++){
                uint32_t ad = st + apart + i*1280 + ks*32;
                LDSM4(ah[i][0],ah[i][1],ah[i][2],ah[i][3], ad);
                LDSM4(al[i][0],al[i][1],al[i][2],al[i][3], ad + 10240);
            }
            #pragma unroll
            for (int jp=0;jp<4;jp++){
                uint32_t bd = st + 20480 + bpart + jp*1280 + ks*32;
                LDSM4(bh[2*jp][0],bh[2*jp][1],bh[2*jp+1][0],bh[2*jp+1][1], bd);
                LDSM4(bl[2*jp][0],bl[2*jp][1],bl[2*jp+1][0],bl[2*jp+1][1], bd + 20480);
            }
            #pragma unroll
            for (int i=0;i<4;i++)
                #pragma unroll
                for (int j=0;j<8;j++){
                    MMA(acc[i][j], ah[i], bh[j]);
                    MMA(acc[i][j], ah[i], bl[j]);
                    MMA(acc[i][j], al[i], bh[j]);
                }
        }
        __syncthreads();
        if (kt + 2 < 32) issue(kt + 2);
    }

    // fused epilogue
    const int mb = m0 + aoff, nb = n0 + boff;
    const int r0 = l>>2, c0 = (l&3)*2;
    const size_t base = (size_t)k*MD;
    if (MODE == 0){
        const float* mu = (k==0) ? g_x : g_states + (size_t)(k-1)*MD;
        const float* bias = bst + k*DIM;
        float* eo = g_eps + base;
        __nv_bfloat16 *eh = g_eh + base, *el = g_el + base;
        #pragma unroll
        for (int i=0;i<4;i++)
            #pragma unroll
            for (int j=0;j<8;j++){
                const int n = nb + j*8 + c0;
                float2 bv = *reinterpret_cast<const float2*>(&bias[n]);
                #pragma unroll
                for (int h=0;h<2;h++){
                    const int m = mb + i*16 + r0 + h*8;
                    float2 mv = *reinterpret_cast<const float2*>(&mu[(size_t)m*DIM + n]);
                    float ex = mv.x - acc[i][j][h*2]   - bv.x;
                    float ey = mv.y - acc[i][j][h*2+1] - bv.y;
                    float2 ov; ov.x = ex; ov.y = ey;
                    *reinterpret_cast<float2*>(&eo[(size_t)m*DIM + n]) = ov;
                    __nv_bfloat16 hx = __float2bfloat16(ex), hy = __float2bfloat16(ey);
                    __nv_bfloat162 hp; hp.x = hx; hp.y = hy;
                    __nv_bfloat162 lp;
                    lp.x = __float2bfloat16(ex - __bfloat162float(hx));
                    lp.y = __float2bfloat16(ey - __bfloat162float(hy));
                    *reinterpret_cast<__nv_bfloat162*>(&eh[(size_t)m*DIM + n]) = hp;
                    *reinterpret_cast<__nv_bfloat162*>(&el[(size_t)m*DIM + n]) = lp;
                }
            }
    } else {
        float* so = g_states + base;
        __nv_bfloat16 *sh = g_sh + base, *sl = g_sl + base;
        const float* en = g_eps + (size_t)(k+1)*MD;
        const bool he = (k < L_-1);
        #pragma unroll
        for (int i=0;i<4;i++)
            #pragma unroll
            for (int j=0;j<8;j++){
                const int n = nb + j*8 + c0;
                #pragma unroll
                for (int h=0;h<2;h++){
                    const int m = mb + i*16 + r0 + h*8;
                    float2 sv = *reinterpret_cast<const float2*>(&so[(size_t)m*DIM + n]);
                    float2 ev;
                    if (he) ev = *reinterpret_cast<const float2*>(&en[(size_t)m*DIM + n]);
                    else { ev.x = 0.f; ev.y = 0.f; }
                    float nx = sv.x + LR*acc[i][j][h*2]   - LR*ev.x;
                    float ny = sv.y + LR*acc[i][j][h*2+1] - LR*ev.y;
                    float2 ov; ov.x = nx; ov.y = ny;
                    *reinterpret_cast<float2*>(&so[(size_t)m*DIM + n]) = ov;
                    __nv_bfloat16 hx = __float2bfloat16(nx), hy = __float2bfloat16(ny);
                    __nv_bfloat162 hp; hp.x = hx; hp.y = hy;
                    __nv_bfloat162 lp;
                    lp.x = __float2bfloat16(nx - __bfloat162float(hx));
                    lp.y = __float2bfloat16(ny - __bfloat162float(hy));
                    *reinterpret_cast<__nv_bfloat162*>(&sh[(size_t)m*DIM + n]) = hp;
                    *reinterpret_cast<__nv_bfloat162*>(&sl[(size_t)m*DIM + n]) = lp;
                }
            }
    }
}

// ---- CE: 128x128 bf16-hi logits tile + online softmax partials ----
// smem: stages [0,40960) (A@0 10240 + B@10240 per stage of 20480);
// logits f32 [40960, 107008) stride 129; s_ob@107008; s_ro@107520; s_tg@108032
__global__ __launch_bounds__(256,1)
void mm_ce(const int* __restrict__ targets, const float* __restrict__ oB){
    extern __shared__ char smem[];
    const uint32_t sb = smem_u32(smem);
    float* ls   = reinterpret_cast<float*>(smem + 40960);
    float* s_ob = reinterpret_cast<float*>(smem + 107008);
    int* s_ro   = reinterpret_cast<int*>(smem + 107520);
    int* s_tg   = reinterpret_cast<int*>(smem + 108032);
    const int tid = threadIdx.x;
    const int split = blockIdx.x, m0 = blockIdx.y*128, n0 = split*128;

    if (tid < 128){
        int rg = m0 + tid;
        if (rg < NROWS){
            int b = rg/(S_-1), s = rg%(S_-1);
            s_ro[tid] = (b*S_ + s)*DIM;
            s_tg[tid] = targets[b*S_ + s + 1];
        } else { s_ro[tid] = 0; s_tg[tid] = -1; }
        s_ob[tid] = oB[n0 + tid];
    }
    __syncthreads();

    const __nv_bfloat16* A3 = g_sh + (size_t)3*MD;
    const __nv_bfloat16* Bw = g_oWh + (size_t)n0*DIM;

    auto issue = [&](int kt){
        const uint32_t st = sb + (uint32_t)(kt&1)*20480u;
        const int k0 = kt*32;
        #pragma unroll
        for (int it = 0; it < 2; it++){
            int c = it*256 + tid, row = c>>2, cc = c&3;
            CP16(st + row*80 + cc*16, A3 + s_ro[row] + k0 + cc*8);
            CP16(st + 10240 + row*80 + cc*16, Bw + (size_t)row*DIM + k0 + cc*8);
        }
        CP_COMMIT();
    };

    const int w = tid>>5, l = tid&31;
    const int wm = w>>2, wn = w&3;
    const int aoff = wm*64, boff = wn*32;
    const uint32_t apart = (uint32_t)((aoff + ((l>>3)&1)*8 + (l&7))*80 + (l>>4)*16);
    const uint32_t bpart = (uint32_t)((boff + (l>>4)*8 + (l&7))*80 + ((l>>3)&1)*16);

    float acc[4][4][4];
    #pragma unroll
    for (int i=0;i<4;i++)
        #pragma unroll
        for (int j=0;j<4;j++)
            #pragma unroll
            for (int q=0;q<4;q++) acc[i][j][q] = 0.f;

    issue(0); issue(1);
    for (int kt = 0; kt < 32; kt++){
        if (kt == 31) CP_WAIT0(); else CP_WAIT1();
        __syncthreads();
        const uint32_t st = sb + (uint32_t)(kt&1)*20480u;
        #pragma unroll
        for (int ks = 0; ks < 2; ks++){
            uint32_t ah[4][4], bh[4][2];
            #pragma unroll
            for (int i=0;i<4;i++){
                uint32_t ad = st + apart + i*1280 + ks*32;
                LDSM4(ah[i][0],ah[i][1],ah[i][2],ah[i][3], ad);
            }
            #pragma unroll
            for (int jp=0;jp<2;jp++){
                uint32_t bd = st + 10240 + bpart + jp*1280 + ks*32;
                LDSM4(bh[2*jp][0],bh[2*jp][1],bh[2*jp+1][0],bh[2*jp+1][1], bd);
            }
            #pragma unroll
            for (int i=0;i<4;i++)
                #pragma unroll
                for (int j=0;j<4;j++)
                    MMA(acc[i][j], ah[i], bh[j]);
        }
        __syncthreads();
        if (kt + 2 < 32) issue(kt + 2);
    }

    // stage logits through smem (row stride 129 floats, conflict-free row scan)
    const int r0 = l>>2, c0 = (l&3)*2;
    #pragma unroll
    for (int i=0;i<4;i++)
        #pragma unroll
        for (int j=0;j<4;j++)
            #pragma unroll
            for (int h=0;h<2;h++){
                int rr = aoff + i*16 + r0 + h*8;
                int cc = boff + j*8 + c0;
                ls[rr*129 + cc]     = acc[i][j][h*2];
                ls[rr*129 + cc + 1] = acc[i][j][h*2+1];
            }
    __syncthreads();

    if (tid < 128){
        const int r = m0 + tid, tg = s_tg[tid];
        float mx = -1e30f;
        #pragma unroll 8
        for (int c = 0; c < 128; c++){
            float v = ls[tid*129 + c] + s_ob[c];
            mx = fmaxf(mx, v);
        }
        float sm = 0.f, tl = -1e30f;
        #pragma unroll 8
        for (int c = 0; c < 128; c++){
            float v = ls[tid*129 + c] + s_ob[c];
            sm += __expf(v - mx);
            if (n0 + c == tg) tl = v;
        }
        if (r < NROWS){
            g_pm[r*NSP + split] = mx;
            g_ps[r*NSP + split] = sm;
            g_pt[r*NSP + split] = tl;
        }
    }
}

// ---- reductions ----
__global__ void pc_reduce_kernel(){
    __shared__ double sm[256];
    double local = 0.0;
    const float4* e4 = reinterpret_cast<const float4*>(g_eps);
    for (int i = blockIdx.x*blockDim.x + threadIdx.x; i < LMD/4; i += gridDim.x*blockDim.x){
        float4 v = e4[i];
        local += (double)v.x*v.x + (double)v.y*v.y + (double)v.z*v.z + (double)v.w*v.w;
    }
    sm[threadIdx.x] = local; __syncthreads();
    for (int s = 128; s > 0; s >>= 1){
        if (threadIdx.x < s) sm[threadIdx.x] += sm[threadIdx.x + s];
        __syncthreads();
    }
    if (threadIdx.x == 0) g_pc_part[blockIdx.x] = sm[0];
}
__global__ void ce_combine_kernel(){
    __shared__ double sm[256];
    double local = 0.0;
    for (int r = blockIdx.x*blockDim.x + threadIdx.x; r < NROWS; r += gridDim.x*blockDim.x){
        float M = -1e30f;
        for (int sp = 0; sp < NSP; sp++) M = fmaxf(M, g_pm[r*NSP + sp]);
        float Z = 0.f;
        for (int sp = 0; sp < NSP; sp++) Z += g_ps[r*NSP + sp]*__expf(g_pm[r*NSP + sp] - M);
        float tl = -1e30f;
        for (int sp = 0; sp < NSP; sp++) tl = fmaxf(tl, g_pt[r*NSP + sp]);
        local += (double)M + log((double)Z) - (double)tl;
    }
    sm[threadIdx.x] = local; __syncthreads();
    for (int s = 128; s > 0; s >>= 1){
        if (threadIdx.x < s) sm[threadIdx.x] += sm[threadIdx.x + s];
        __syncthreads();
    }
    if (threadIdx.x == 0) g_ce_part[blockIdx.x] = sm[0];
}
__global__ void finalize_kernel(float* out){
    double pc = 0.0, ce = 0.0;
    for (int i = 0; i < NPCB; i++) pc += g_pc_part[i];
    for (int i = 0; i < NCEB; i++) ce += g_ce_part[i];
    out[0] = (float)(ce/(double)NROWS);
    out[1] = (float)(pc/(double)LMD);
}

// ---- launch ----
extern "C" void kernel_launch(void* const* d_in, const int* in_sizes, int n_in,
                              void* d_out, int out_size){
    const int*   input_ids   = (const int*)d_in[0];
    const int*   targets     = (const int*)d_in[1];
    const float* emb         = (const float*)d_in[2];
    const float* W_stack     = (const float*)d_in[3];
    const float* b_stack     = (const float*)d_in[4];
    const float* out_W       = (const float*)d_in[5];
    const float* out_b       = (const float*)d_in[6];
    const float* states_init = (const float*)d_in[7];
    float* out = (float*)d_out;

    constexpr int GSMEM = 2*61440;     // 120 KB
    constexpr int CSMEM = 108544;      // ~106 KB
    cudaFuncSetAttribute(mm_step<0>, cudaFuncAttributeMaxDynamicSharedMemorySize, GSMEM);
    cudaFuncSetAttribute(mm_step<1>, cudaFuncAttributeMaxDynamicSharedMemorySize, GSMEM);
    cudaFuncSetAttribute(mm_ce,      cudaFuncAttributeMaxDynamicSharedMemorySize, CSMEM);

    split_states_kernel<<<LMD/256, 256>>>(states_init);
    gather_kernel<<<M_, 256>>>(input_ids, emb);
    split_w_kernel<<<dim3(32,32,L_), dim3(32,8)>>>(W_stack);
    split_ow_kernel<<<(V_*DIM)/256, 256>>>(out_W);

    dim3 gg(DIM/256, M_/128);   // (4, 32) = 128 blocks
    for (int step = 0; step < STEPS; step++){
        for (int k = 0; k < L_; k++) mm_step<0><<<gg, 256, GSMEM>>>(k, b_stack);
        for (int k = 0; k < L_; k++) mm_step<1><<<gg, 256, GSMEM>>>(k, b_stack);
    }
    for (int k = 0; k < L_; k++) mm_step<0><<<gg, 256, GSMEM>>>(k, b_stack);

    pc_reduce_kernel<<<NPCB, 256>>>();
    mm_ce<<<dim3(NSP, M_/128), 256, CSMEM>>>(targets, out_b);
    ce_combine_kernel<<<NCEB, 256>>>();
    finalize_kernel<<<1, 1>>>(out);
}

// round 6
// speedup vs baseline: 3.2552x; 1.0146x over previous
#include <cuda_runtime.h>
#include <cuda_bf16.h>
#include <math.h>
#include <stdint.h>

#define DIM 1024
constexpr int B_ = 8, S_ = 512, L_ = 4;
constexpr int M_ = B_ * S_;
constexpr int V_ = 32000;
constexpr int STEPS = 8;
constexpr float LR = 0.1f;
constexpr int MD = M_ * DIM, LMD = L_ * MD;
constexpr int NROWS = B_ * (S_ - 1);
constexpr int NSP = V_ / 128;     // 250
constexpr int NPCB = 256, NCEB = 16;

__device__ float g_x[MD];
__device__ float g_states[LMD];
__device__ float g_eps[LMD];
__device__ __nv_bfloat16 g_sh[LMD], g_sl[LMD], g_eh[LMD], g_el[LMD];
__device__ __nv_bfloat16 g_Wh[L_*DIM*DIM], g_Wl[L_*DIM*DIM];
__device__ __nv_bfloat16 g_Wth[L_*DIM*DIM], g_Wtl[L_*DIM*DIM];
__device__ __nv_bfloat16 g_oWh[V_*DIM];
__device__ float g_pm[4096*NSP], g_ps[4096*NSP], g_pt[4096*NSP];
__device__ double g_pc_part[NPCB], g_ce_part[NCEB];

// ---- baseline-ISA helpers ----
__device__ __forceinline__ uint32_t smem_u32(const void* p){
    uint32_t a; asm("{ .reg .u64 t; cvta.to.shared.u64 t, %1; cvt.u32.u64 %0, t; }":"=r"(a):"l"(p)); return a;
}
#define CP16(dst, src) \
    asm volatile("cp.async.cg.shared.global [%0], [%1], 16;" \
        :: "r"(dst), "l"(__cvta_generic_to_global(src)) : "memory")
#define CP_COMMIT() asm volatile("cp.async.commit_group;" ::: "memory")
#define CP_WAIT1()  asm volatile("cp.async.wait_group 1;" ::: "memory")
#define CP_WAIT0()  asm volatile("cp.async.wait_group 0;" ::: "memory")
#define LDSM4(r0,r1,r2,r3,addr) \
    asm volatile("ldmatrix.sync.aligned.m8n8.x4.shared.b16 {%0,%1,%2,%3}, [%4];" \
        : "=r"(r0),"=r"(r1),"=r"(r2),"=r"(r3) : "r"(addr))
#define MMA(d, a, b) \
    asm volatile("mma.sync.aligned.m16n8k16.row.col.f32.bf16.bf16.f32 " \
        "{%0,%1,%2,%3},{%4,%5,%6,%7},{%8,%9},{%0,%1,%2,%3};" \
        : "+f"((d)[0]),"+f"((d)[1]),"+f"((d)[2]),"+f"((d)[3]) \
        : "r"((a)[0]),"r"((a)[1]),"r"((a)[2]),"r"((a)[3]),"r"((b)[0]),"r"((b)[1]))

// ---- prep kernels ----
__global__ void gather_kernel(const int* __restrict__ ids, const float* __restrict__ emb){
    int row = blockIdx.x, id = ids[row];
    reinterpret_cast<float4*>(g_x + (size_t)row*DIM)[threadIdx.x] =
        reinterpret_cast<const float4*>(emb + (size_t)id*DIM)[threadIdx.x];
}
__global__ void split_states_kernel(const float* __restrict__ si){
    int i = blockIdx.x*blockDim.x + threadIdx.x;
    float v = si[i];
    g_states[i] = v;
    __nv_bfloat16 h = __float2bfloat16(v);
    g_sh[i] = h; g_sl[i] = __float2bfloat16(v - __bfloat162float(h));
}
__global__ void split_w_kernel(const float* __restrict__ W){
    __shared__ float tile[32][33];
    int l = blockIdx.z, i0 = blockIdx.y*32, j0 = blockIdx.x*32;
    int tx = threadIdx.x, ty = threadIdx.y;
    const float* Wb = W + (size_t)l*DIM*DIM;
    #pragma unroll
    for (int r = 0; r < 4; r++){
        int i = i0 + ty + r*8;
        float w = Wb[(size_t)i*DIM + j0 + tx];
        __nv_bfloat16 h = __float2bfloat16(w);
        size_t o = (size_t)l*DIM*DIM + (size_t)i*DIM + j0 + tx;
        g_Wh[o] = h; g_Wl[o] = __float2bfloat16(w - __bfloat162float(h));
        tile[ty + r*8][tx] = w;
    }
    __syncthreads();
    #pragma unroll
    for (int r = 0; r < 4; r++){
        int jr = ty + r*8;
        float w = tile[tx][jr];
        __nv_bfloat16 h = __float2bfloat16(w);
        size_t o = (size_t)l*DIM*DIM + (size_t)(j0+jr)*DIM + i0 + tx;
        g_Wth[o] = h; g_Wtl[o] = __float2bfloat16(w - __bfloat162float(h));
    }
}
__global__ void split_ow_kernel(const float* __restrict__ oW){
    int i = blockIdx.x*blockDim.x + threadIdx.x;
    g_oWh[i] = __float2bfloat16(oW[i]);
}

// ---- mma.sync step GEMM: block 128x256, BK=32, 8 warps of 64x64 ----
// 3-stage cp.async pipeline, one __syncthreads per K-tile, layers fused via z.
// MODE0: eps_k = mu_k - states_k @ W_k^T - b_k
// MODE1: states_k += LR*(eps_k @ W_k) - LR*eps_{k+1}
// stage (61440B): Ah@0 Al@10240 Bh@20480 Bl@40960; rows padded to 80B.
template<int MODE>
__global__ __launch_bounds__(256,1)
void mm_step(const float* __restrict__ bst){
    extern __shared__ char smem[];
    const uint32_t sb = smem_u32(smem);
    const int tid = threadIdx.x;
    const int k = blockIdx.z;
    const int m0 = blockIdx.y*128, n0 = blockIdx.x*256;
    const __nv_bfloat16* Ah = (MODE==0?g_sh:g_eh) + (size_t)k*MD + (size_t)m0*DIM;
    const __nv_bfloat16* Al = (MODE==0?g_sl:g_el) + (size_t)k*MD + (size_t)m0*DIM;
    const __nv_bfloat16* Bh = (MODE==0?g_Wh:g_Wth) + (size_t)k*DIM*DIM + (size_t)n0*DIM;
    const __nv_bfloat16* Bl = (MODE==0?g_Wl:g_Wtl) + (size_t)k*DIM*DIM + (size_t)n0*DIM;

    auto issue = [&](int kt){
        const uint32_t st = sb + (uint32_t)(kt%3)*61440u;
        const int k0 = kt*32;
        #pragma unroll
        for (int it = 0; it < 2; it++){      // A: 512 chunks
            int c = it*256 + tid, row = c>>2, cc = c&3;
            uint32_t d = st + row*80 + cc*16;
            CP16(d, Ah + (size_t)row*DIM + k0 + cc*8);
            CP16(d + 10240, Al + (size_t)row*DIM + k0 + cc*8);
        }
        #pragma unroll
        for (int it = 0; it < 4; it++){      // B: 1024 chunks
            int c = it*256 + tid, row = c>>2, cc = c&3;
            uint32_t d = st + 20480 + row*80 + cc*16;
            CP16(d, Bh + (size_t)row*DIM + k0 + cc*8);
            CP16(d + 20480, Bl + (size_t)row*DIM + k0 + cc*8);
        }
        CP_COMMIT();
    };

    const int w = tid>>5, l = tid&31;
    const int wm = w>>2, wn = w&3;
    const int aoff = wm*64, boff = wn*64;
    const uint32_t apart = (uint32_t)((aoff + ((l>>3)&1)*8 + (l&7))*80 + (l>>4)*16);
    const uint32_t bpart = (uint32_t)((boff + (l>>4)*8 + (l&7))*80 + ((l>>3)&1)*16);

    float acc[4][8][4];
    #pragma unroll
    for (int i=0;i<4;i++)
        #pragma unroll
        for (int j=0;j<8;j++)
            #pragma unroll
            for (int q=0;q<4;q++) acc[i][j][q] = 0.f;

    issue(0); issue(1);
    for (int kt = 0; kt < 32; kt++){
        if (kt == 31) CP_WAIT0(); else CP_WAIT1();
        __syncthreads();
        if (kt + 2 < 32) issue(kt + 2);   // writes stage (kt+2)%3 == (kt-1)%3: all
                                          // readers of it passed the sync above
        const uint32_t st = sb + (uint32_t)(kt%3)*61440u;
        #pragma unroll
        for (int ks = 0; ks < 2; ks++){
            uint32_t ah[4][4], al[4][4], bh[8][2], bl[8][2];
            #pragma unroll
            for (int i=0;i<4;i++){
                uint32_t ad = st + apart + i*1280 + ks*32;
                LDSM4(ah[i][0],ah[i][1],ah[i][2],ah[i][3], ad);
                LDSM4(al[i][0],al[i][1],al[i][2],al[i][3], ad + 10240);
            }
            #pragma unroll
            for (int jp=0;jp<4;jp++){
                uint32_t bd = st + 20480 + bpart + jp*1280 + ks*32;
                LDSM4(bh[2*jp][0],bh[2*jp][1],bh[2*jp+1][0],bh[2*jp+1][1], bd);
                LDSM4(bl[2*jp][0],bl[2*jp][1],bl[2*jp+1][0],bl[2*jp+1][1], bd + 20480);
            }
            #pragma unroll
            for (int i=0;i<4;i++)
                #pragma unroll
                for (int j=0;j<8;j++){
                    MMA(acc[i][j], ah[i], bh[j]);
                    MMA(acc[i][j], ah[i], bl[j]);
                    MMA(acc[i][j], al[i], bh[j]);
                }
        }
    }

    // fused epilogue
    const int mb = m0 + aoff, nb = n0 + boff;
    const int r0 = l>>2, c0 = (l&3)*2;
    const size_t base = (size_t)k*MD;
    if (MODE == 0){
        const float* mu = (k==0) ? g_x : g_states + (size_t)(k-1)*MD;
        const float* bias = bst + k*DIM;
        float* eo = g_eps + base;
        __nv_bfloat16 *eh = g_eh + base, *el = g_el + base;
        #pragma unroll
        for (int i=0;i<4;i++)
            #pragma unroll
            for (int j=0;j<8;j++){
                const int n = nb + j*8 + c0;
                float2 bv = *reinterpret_cast<const float2*>(&bias[n]);
                #pragma unroll
                for (int h=0;h<2;h++){
                    const int m = mb + i*16 + r0 + h*8;
                    float2 mv = *reinterpret_cast<const float2*>(&mu[(size_t)m*DIM + n]);
                    float ex = mv.x - acc[i][j][h*2]   - bv.x;
                    float ey = mv.y - acc[i][j][h*2+1] - bv.y;
                    float2 ov; ov.x = ex; ov.y = ey;
                    *reinterpret_cast<float2*>(&eo[(size_t)m*DIM + n]) = ov;
                    __nv_bfloat16 hx = __float2bfloat16(ex), hy = __float2bfloat16(ey);
                    __nv_bfloat162 hp; hp.x = hx; hp.y = hy;
                    __nv_bfloat162 lp;
                    lp.x = __float2bfloat16(ex - __bfloat162float(hx));
                    lp.y = __float2bfloat16(ey - __bfloat162float(hy));
                    *reinterpret_cast<__nv_bfloat162*>(&eh[(size_t)m*DIM + n]) = hp;
                    *reinterpret_cast<__nv_bfloat162*>(&el[(size_t)m*DIM + n]) = lp;
                }
            }
    } else {
        float* so = g_states + base;
        __nv_bfloat16 *sh = g_sh + base, *sl = g_sl + base;
        const float* en = g_eps + (size_t)(k+1)*MD;
        const bool he = (k < L_-1);
        #pragma unroll
        for (int i=0;i<4;i++)
            #pragma unroll
            for (int j=0;j<8;j++){
                const int n = nb + j*8 + c0;
                #pragma unroll
                for (int h=0;h<2;h++){
                    const int m = mb + i*16 + r0 + h*8;
                    float2 sv = *reinterpret_cast<const float2*>(&so[(size_t)m*DIM + n]);
                    float2 ev;
                    if (he) ev = *reinterpret_cast<const float2*>(&en[(size_t)m*DIM + n]);
                    else { ev.x = 0.f; ev.y = 0.f; }
                    float nx = sv.x + LR*acc[i][j][h*2]   - LR*ev.x;
                    float ny = sv.y + LR*acc[i][j][h*2+1] - LR*ev.y;
                    float2 ov; ov.x = nx; ov.y = ny;
                    *reinterpret_cast<float2*>(&so[(size_t)m*DIM + n]) = ov;
                    __nv_bfloat16 hx = __float2bfloat16(nx), hy = __float2bfloat16(ny);
                    __nv_bfloat162 hp; hp.x = hx; hp.y = hy;
                    __nv_bfloat162 lp;
                    lp.x = __float2bfloat16(nx - __bfloat162float(hx));
                    lp.y = __float2bfloat16(ny - __bfloat162float(hy));
                    *reinterpret_cast<__nv_bfloat162*>(&sh[(size_t)m*DIM + n]) = hp;
                    *reinterpret_cast<__nv_bfloat162*>(&sl[(size_t)m*DIM + n]) = lp;
                }
            }
    }
}

// ---- CE: 128x128 bf16-hi logits tile + online softmax partials ----
// smem: 3 stages [0,61440) (A@0 + B@10240 per 20480 stage);
// logits f32 @61440 stride 129 (66048B); s_ob@127488; s_ro@128000; s_tg@128512
__global__ __launch_bounds__(256,1)
void mm_ce(const int* __restrict__ targets, const float* __restrict__ oB){
    extern __shared__ char smem[];
    const uint32_t sb = smem_u32(smem);
    float* ls   = reinterpret_cast<float*>(smem + 61440);
    float* s_ob = reinterpret_cast<float*>(smem + 127488);
    int* s_ro   = reinterpret_cast<int*>(smem + 128000);
    int* s_tg   = reinterpret_cast<int*>(smem + 128512);
    const int tid = threadIdx.x;
    const int split = blockIdx.x, m0 = blockIdx.y*128, n0 = split*128;

    if (tid < 128){
        int rg = m0 + tid;
        if (rg < NROWS){
            int b = rg/(S_-1), s = rg%(S_-1);
            s_ro[tid] = (b*S_ + s)*DIM;
            s_tg[tid] = targets[b*S_ + s + 1];
        } else { s_ro[tid] = 0; s_tg[tid] = -1; }
        s_ob[tid] = oB[n0 + tid];
    }
    __syncthreads();

    const __nv_bfloat16* A3 = g_sh + (size_t)3*MD;
    const __nv_bfloat16* Bw = g_oWh + (size_t)n0*DIM;

    auto issue = [&](int kt){
        const uint32_t st = sb + (uint32_t)(kt%3)*20480u;
        const int k0 = kt*32;
        #pragma unroll
        for (int it = 0; it < 2; it++){
            int c = it*256 + tid, row = c>>2, cc = c&3;
            CP16(st + row*80 + cc*16, A3 + s_ro[row] + k0 + cc*8);
            CP16(st + 10240 + row*80 + cc*16, Bw + (size_t)row*DIM + k0 + cc*8);
        }
        CP_COMMIT();
    };

    const int w = tid>>5, l = tid&31;
    const int wm = w>>2, wn = w&3;
    const int aoff = wm*64, boff = wn*32;
    const uint32_t apart = (uint32_t)((aoff + ((l>>3)&1)*8 + (l&7))*80 + (l>>4)*16);
    const uint32_t bpart = (uint32_t)((boff + (l>>4)*8 + (l&7))*80 + ((l>>3)&1)*16);

    float acc[4][4][4];
    #pragma unroll
    for (int i=0;i<4;i++)
        #pragma unroll
        for (int j=0;j<4;j++)
            #pragma unroll
            for (int q=0;q<4;q++) acc[i][j][q] = 0.f;

    issue(0); issue(1);
    for (int kt = 0; kt < 32; kt++){
        if (kt == 31) CP_WAIT0(); else CP_WAIT1();
        __syncthreads();
        if (kt + 2 < 32) issue(kt + 2);
        const uint32_t st = sb + (uint32_t)(kt%3)*20480u;
        #pragma unroll
        for (int ks = 0; ks < 2; ks++){
            uint32_t ah[4][4], bh[4][2];
            #pragma unroll
            for (int i=0;i<4;i++){
                uint32_t ad = st + apart + i*1280 + ks*32;
                LDSM4(ah[i][0],ah[i][1],ah[i][2],ah[i][3], ad);
            }
            #pragma unroll
            for (int jp=0;jp<2;jp++){
                uint32_t bd = st + 10240 + bpart + jp*1280 + ks*32;
                LDSM4(bh[2*jp][0],bh[2*jp][1],bh[2*jp+1][0],bh[2*jp+1][1], bd);
            }
            #pragma unroll
            for (int i=0;i<4;i++)
                #pragma unroll
                for (int j=0;j<4;j++)
                    MMA(acc[i][j], ah[i], bh[j]);
        }
    }

    const int r0 = l>>2, c0 = (l&3)*2;
    #pragma unroll
    for (int i=0;i<4;i++)
        #pragma unroll
        for (int j=0;j<4;j++)
            #pragma unroll
            for (int h=0;h<2;h++){
                int rr = aoff + i*16 + r0 + h*8;
                int cc = boff + j*8 + c0;
                ls[rr*129 + cc]     = acc[i][j][h*2];
                ls[rr*129 + cc + 1] = acc[i][j][h*2+1];
            }
    __syncthreads();

    if (tid < 128){
        const int r = m0 + tid, tg = s_tg[tid];
        float mx = -1e30f;
        #pragma unroll 8
        for (int c = 0; c < 128; c++){
            float v = ls[tid*129 + c] + s_ob[c];
            mx = fmaxf(mx, v);
        }
        float sm = 0.f, tl = -1e30f;
        #pragma unroll 8
        for (int c = 0; c < 128; c++){
            float v = ls[tid*129 + c] + s_ob[c];
            sm += __expf(v - mx);
            if (n0 + c == tg) tl = v;
        }
        if (r < NROWS){
            g_pm[r*NSP + split] = mx;
            g_ps[r*NSP + split] = sm;
            g_pt[r*NSP + split] = tl;
        }
    }
}

// ---- reductions ----
__global__ void pc_reduce_kernel(){
    __shared__ double sm[256];
    double local = 0.0;
    const float4* e4 = reinterpret_cast<const float4*>(g_eps);
    for (int i = blockIdx.x*blockDim.x + threadIdx.x; i < LMD/4; i += gridDim.x*blockDim.x){
        float4 v = e4[i];
        local += (double)v.x*v.x + (double)v.y*v.y + (double)v.z*v.z + (double)v.w*v.w;
    }
    sm[threadIdx.x] = local; __syncthreads();
    for (int s = 128; s > 0; s >>= 1){
        if (threadIdx.x < s) sm[threadIdx.x] += sm[threadIdx.x + s];
        __syncthreads();
    }
    if (threadIdx.x == 0) g_pc_part[blockIdx.x] = sm[0];
}
__global__ void ce_combine_kernel(){
    __shared__ double sm[256];
    double local = 0.0;
    for (int r = blockIdx.x*blockDim.x + threadIdx.x; r < NROWS; r += gridDim.x*blockDim.x){
        float M = -1e30f;
        for (int sp = 0; sp < NSP; sp++) M = fmaxf(M, g_pm[r*NSP + sp]);
        float Z = 0.f;
        for (int sp = 0; sp < NSP; sp++) Z += g_ps[r*NSP + sp]*__expf(g_pm[r*NSP + sp] - M);
        float tl = -1e30f;
        for (int sp = 0; sp < NSP; sp++) tl = fmaxf(tl, g_pt[r*NSP + sp]);
        local += (double)M + log((double)Z) - (double)tl;
    }
    sm[threadIdx.x] = local; __syncthreads();
    for (int s = 128; s > 0; s >>= 1){
        if (threadIdx.x < s) sm[threadIdx.x] += sm[threadIdx.x + s];
        __syncthreads();
    }
    if (threadIdx.x == 0) g_ce_part[blockIdx.x] = sm[0];
}
__global__ void finalize_kernel(float* out){
    double pc = 0.0, ce = 0.0;
    for (int i = 0; i < NPCB; i++) pc += g_pc_part[i];
    for (int i = 0; i < NCEB; i++) ce += g_ce_part[i];
    out[0] = (float)(ce/(double)NROWS);
    out[1] = (float)(pc/(double)LMD);
}

// ---- launch ----
extern "C" void kernel_launch(void* const* d_in, const int* in_sizes, int n_in,
                              void* d_out, int out_size){
    const int*   input_ids   = (const int*)d_in[0];
    const int*   targets     = (const int*)d_in[1];
    const float* emb         = (const float*)d_in[2];
    const float* W_stack     = (const float*)d_in[3];
    const float* b_stack     = (const float*)d_in[4];
    const float* out_W       = (const float*)d_in[5];
    const float* out_b       = (const float*)d_in[6];
    const float* states_init = (const float*)d_in[7];
    float* out = (float*)d_out;

    constexpr int GSMEM = 3*61440;     // 180 KB
    constexpr int CSMEM = 129024;      // ~126 KB
    cudaFuncSetAttribute(mm_step<0>, cudaFuncAttributeMaxDynamicSharedMemorySize, GSMEM);
    cudaFuncSetAttribute(mm_step<1>, cudaFuncAttributeMaxDynamicSharedMemorySize, GSMEM);
    cudaFuncSetAttribute(mm_ce,      cudaFuncAttributeMaxDynamicSharedMemorySize, CSMEM);

    split_states_kernel<<<LMD/256, 256>>>(states_init);
    gather_kernel<<<M_, 256>>>(input_ids, emb);
    split_w_kernel<<<dim3(32,32,L_), dim3(32,8)>>>(W_stack);
    split_ow_kernel<<<(V_*DIM)/256, 256>>>(out_W);

    dim3 gg(DIM/256, M_/128, L_);   // (4, 32, 4) = 512 blocks, layers fused
    for (int step = 0; step < STEPS; step++){
        mm_step<0><<<gg, 256, GSMEM>>>(b_stack);
        mm_step<1><<<gg, 256, GSMEM>>>(b_stack);
    }
    mm_step<0><<<gg, 256, GSMEM>>>(b_stack);

    pc_reduce_kernel<<<NPCB, 256>>>();
    mm_ce<<<dim3(NSP, M_/128), 256, CSMEM>>>(targets, out_b);
    ce_combine_kernel<<<NCEB, 256>>>();
    finalize_kernel<<<1, 1>>>(out);
}

// round 7
// speedup vs baseline: 3.3123x; 1.0175x over previous
#include <cuda_runtime.h>
#include <cuda_bf16.h>
#include <math.h>
#include <stdint.h>

#define DIM 1024
constexpr int B_ = 8, S_ = 512, L_ = 4;
constexpr int M_ = B_ * S_;
constexpr int V_ = 32000;
constexpr int STEPS = 8;
constexpr float LR = 0.1f;
constexpr int MD = M_ * DIM, LMD = L_ * MD;
constexpr int NROWS = B_ * (S_ - 1);
constexpr int NSP = V_ / 128;     // 250
constexpr int NPCB = 256, NCEB = 16;

__device__ float g_x[MD];
__device__ float g_states[LMD];
__device__ __nv_bfloat16 g_sh[LMD], g_sl[LMD], g_eh[LMD], g_el[LMD];
__device__ __nv_bfloat16 g_Wh[L_*DIM*DIM], g_Wl[L_*DIM*DIM];
__device__ __nv_bfloat16 g_Wth[L_*DIM*DIM], g_Wtl[L_*DIM*DIM];
__device__ __nv_bfloat16 g_oWh[V_*DIM];
__device__ float g_pm[4096*NSP], g_ps[4096*NSP], g_pt[4096*NSP];
__device__ double g_pc_part[NPCB], g_ce_part[NCEB];

// ---- baseline-ISA helpers ----
__device__ __forceinline__ uint32_t smem_u32(const void* p){
    uint32_t a; asm("{ .reg .u64 t; cvta.to.shared.u64 t, %1; cvt.u32.u64 %0, t; }":"=r"(a):"l"(p)); return a;
}
#define CP16(dst, src) \
    asm volatile("cp.async.cg.shared.global [%0], [%1], 16;" \
        :: "r"(dst), "l"(__cvta_generic_to_global(src)) : "memory")
#define CP_COMMIT() asm volatile("cp.async.commit_group;" ::: "memory")
#define CP_WAIT1()  asm volatile("cp.async.wait_group 1;" ::: "memory")
#define CP_WAIT0()  asm volatile("cp.async.wait_group 0;" ::: "memory")
#define LDSM4(r0,r1,r2,r3,addr) \
    asm volatile("ldmatrix.sync.aligned.m8n8.x4.shared.b16 {%0,%1,%2,%3}, [%4];" \
        : "=r"(r0),"=r"(r1),"=r"(r2),"=r"(r3) : "r"(addr))
#define MMA(d, a, b) \
    asm volatile("mma.sync.aligned.m16n8k16.row.col.f32.bf16.bf16.f32 " \
        "{%0,%1,%2,%3},{%4,%5,%6,%7},{%8,%9},{%0,%1,%2,%3};" \
        : "+f"((d)[0]),"+f"((d)[1]),"+f"((d)[2]),"+f"((d)[3]) \
        : "r"((a)[0]),"r"((a)[1]),"r"((a)[2]),"r"((a)[3]),"r"((b)[0]),"r"((b)[1]))

// ---- prep kernels ----
__global__ void gather_kernel(const int* __restrict__ ids, const float* __restrict__ emb){
    int row = blockIdx.x, id = ids[row];
    reinterpret_cast<float4*>(g_x + (size_t)row*DIM)[threadIdx.x] =
        reinterpret_cast<const float4*>(emb + (size_t)id*DIM)[threadIdx.x];
}
__global__ void split_states_kernel(const float* __restrict__ si){
    int i = blockIdx.x*blockDim.x + threadIdx.x;   // over LMD/4
    float4 v = reinterpret_cast<const float4*>(si)[i];
    reinterpret_cast<float4*>(g_states)[i] = v;
    float e[4] = {v.x, v.y, v.z, v.w};
    __nv_bfloat162 hp[2], lp[2];
    #pragma unroll
    for (int q = 0; q < 2; q++){
        __nv_bfloat16 h0 = __float2bfloat16(e[q*2]), h1 = __float2bfloat16(e[q*2+1]);
        hp[q].x = h0; hp[q].y = h1;
        lp[q].x = __float2bfloat16(e[q*2]   - __bfloat162float(h0));
        lp[q].y = __float2bfloat16(e[q*2+1] - __bfloat162float(h1));
    }
    reinterpret_cast<uint2*>(g_sh)[i] = *reinterpret_cast<uint2*>(hp);
    reinterpret_cast<uint2*>(g_sl)[i] = *reinterpret_cast<uint2*>(lp);
}
__global__ void split_w_kernel(const float* __restrict__ W){
    __shared__ float tile[32][33];
    int l = blockIdx.z, i0 = blockIdx.y*32, j0 = blockIdx.x*32;
    int tx = threadIdx.x, ty = threadIdx.y;
    const float* Wb = W + (size_t)l*DIM*DIM;
    #pragma unroll
    for (int r = 0; r < 4; r++){
        int i = i0 + ty + r*8;
        float w = Wb[(size_t)i*DIM + j0 + tx];
        __nv_bfloat16 h = __float2bfloat16(w);
        size_t o = (size_t)l*DIM*DIM + (size_t)i*DIM + j0 + tx;
        g_Wh[o] = h; g_Wl[o] = __float2bfloat16(w - __bfloat162float(h));
        tile[ty + r*8][tx] = w;
    }
    __syncthreads();
    #pragma unroll
    for (int r = 0; r < 4; r++){
        int jr = ty + r*8;
        float w = tile[tx][jr];
        __nv_bfloat16 h = __float2bfloat16(w);
        size_t o = (size_t)l*DIM*DIM + (size_t)(j0+jr)*DIM + i0 + tx;
        g_Wth[o] = h; g_Wtl[o] = __float2bfloat16(w - __bfloat162float(h));
    }
}
__global__ void split_ow_kernel(const float* __restrict__ oW){
    int i = blockIdx.x*blockDim.x + threadIdx.x;   // over V*DIM/4
    float4 v = reinterpret_cast<const float4*>(oW)[i];
    __nv_bfloat162 hp[2];
    hp[0].x = __float2bfloat16(v.x); hp[0].y = __float2bfloat16(v.y);
    hp[1].x = __float2bfloat16(v.z); hp[1].y = __float2bfloat16(v.w);
    reinterpret_cast<uint2*>(g_oWh)[i] = *reinterpret_cast<uint2*>(hp);
}

// ---- mma.sync step GEMM: block 128x256, BK=32, 8 warps of 64x64 ----
// 3-stage cp.async pipeline; chains broken: pass-major MMA order (bit-identical
// per-accumulator sequence ahbh, ahbl, albh). Layers fused via z.
// MODE0: eps_k = mu_k - states_k @ W_k^T - b_k   (eps stored bf16 hi/lo only)
// MODE1: states_k += LR*(eps_k @ W_k) - LR*eps_{k+1}
template<int MODE>
__global__ __launch_bounds__(256,1)
void mm_step(const float* __restrict__ bst){
    extern __shared__ char smem[];
    const uint32_t sb = smem_u32(smem);
    const int tid = threadIdx.x;
    const int k = blockIdx.z;
    const int m0 = blockIdx.y*128, n0 = blockIdx.x*256;
    const __nv_bfloat16* Ah = (MODE==0?g_sh:g_eh) + (size_t)k*MD + (size_t)m0*DIM;
    const __nv_bfloat16* Al = (MODE==0?g_sl:g_el) + (size_t)k*MD + (size_t)m0*DIM;
    const __nv_bfloat16* Bh = (MODE==0?g_Wh:g_Wth) + (size_t)k*DIM*DIM + (size_t)n0*DIM;
    const __nv_bfloat16* Bl = (MODE==0?g_Wl:g_Wtl) + (size_t)k*DIM*DIM + (size_t)n0*DIM;

    auto issue = [&](int kt){
        const uint32_t st = sb + (uint32_t)(kt%3)*61440u;
        const int k0 = kt*32;
        #pragma unroll
        for (int it = 0; it < 2; it++){
            int c = it*256 + tid, row = c>>2, cc = c&3;
            uint32_t d = st + row*80 + cc*16;
            CP16(d, Ah + (size_t)row*DIM + k0 + cc*8);
            CP16(d + 10240, Al + (size_t)row*DIM + k0 + cc*8);
        }
        #pragma unroll
        for (int it = 0; it < 4; it++){
            int c = it*256 + tid, row = c>>2, cc = c&3;
            uint32_t d = st + 20480 + row*80 + cc*16;
            CP16(d, Bh + (size_t)row*DIM + k0 + cc*8);
            CP16(d + 20480, Bl + (size_t)row*DIM + k0 + cc*8);
        }
        CP_COMMIT();
    };

    const int w = tid>>5, l = tid&31;
    const int wm = w>>2, wn = w&3;
    const int aoff = wm*64, boff = wn*64;
    const uint32_t apart = (uint32_t)((aoff + ((l>>3)&1)*8 + (l&7))*80 + (l>>4)*16);
    const uint32_t bpart = (uint32_t)((boff + (l>>4)*8 + (l&7))*80 + ((l>>3)&1)*16);

    float acc[4][8][4];
    #pragma unroll
    for (int i=0;i<4;i++)
        #pragma unroll
        for (int j=0;j<8;j++)
            #pragma unroll
            for (int q=0;q<4;q++) acc[i][j][q] = 0.f;

    issue(0); issue(1);
    for (int kt = 0; kt < 32; kt++){
        if (kt == 31) CP_WAIT0(); else CP_WAIT1();
        __syncthreads();
        if (kt + 2 < 32) issue(kt + 2);
        const uint32_t st = sb + (uint32_t)(kt%3)*61440u;
        #pragma unroll
        for (int ks = 0; ks < 2; ks++){
            uint32_t ah[4][4], al[4][4], bh[8][2], bl[8][2];
            #pragma unroll
            for (int i=0;i<4;i++){
                uint32_t ad = st + apart + i*1280 + ks*32;
                LDSM4(ah[i][0],ah[i][1],ah[i][2],ah[i][3], ad);
                LDSM4(al[i][0],al[i][1],al[i][2],al[i][3], ad + 10240);
            }
            #pragma unroll
            for (int jp=0;jp<4;jp++){
                uint32_t bd = st + 20480 + bpart + jp*1280 + ks*32;
                LDSM4(bh[2*jp][0],bh[2*jp][1],bh[2*jp+1][0],bh[2*jp+1][1], bd);
                LDSM4(bl[2*jp][0],bl[2*jp][1],bl[2*jp+1][0],bl[2*jp+1][1], bd + 20480);
            }
            // pass-major: 32 independent MMAs between touches of the same acc
            #pragma unroll
            for (int i=0;i<4;i++)
                #pragma unroll
                for (int j=0;j<8;j++) MMA(acc[i][j], ah[i], bh[j]);
            #pragma unroll
            for (int i=0;i<4;i++)
                #pragma unroll
                for (int j=0;j<8;j++) MMA(acc[i][j], ah[i], bl[j]);
            #pragma unroll
            for (int i=0;i<4;i++)
                #pragma unroll
                for (int j=0;j<8;j++) MMA(acc[i][j], al[i], bh[j]);
        }
    }

    // fused epilogue
    const int mb = m0 + aoff, nb = n0 + boff;
    const int r0 = l>>2, c0 = (l&3)*2;
    const size_t base = (size_t)k*MD;
    if (MODE == 0){
        const float* mu = (k==0) ? g_x : g_states + (size_t)(k-1)*MD;
        const float* bias = bst + k*DIM;
        __nv_bfloat16 *eh = g_eh + base, *el = g_el + base;
        #pragma unroll
        for (int i=0;i<4;i++)
            #pragma unroll
            for (int j=0;j<8;j++){
                const int n = nb + j*8 + c0;
                float2 bv = *reinterpret_cast<const float2*>(&bias[n]);
                #pragma unroll
                for (int h=0;h<2;h++){
                    const int m = mb + i*16 + r0 + h*8;
                    float2 mv = *reinterpret_cast<const float2*>(&mu[(size_t)m*DIM + n]);
                    float ex = mv.x - acc[i][j][h*2]   - bv.x;
                    float ey = mv.y - acc[i][j][h*2+1] - bv.y;
                    __nv_bfloat16 hx = __float2bfloat16(ex), hy = __float2bfloat16(ey);
                    __nv_bfloat162 hp; hp.x = hx; hp.y = hy;
                    __nv_bfloat162 lp;
                    lp.x = __float2bfloat16(ex - __bfloat162float(hx));
                    lp.y = __float2bfloat16(ey - __bfloat162float(hy));
                    *reinterpret_cast<__nv_bfloat162*>(&eh[(size_t)m*DIM + n]) = hp;
                    *reinterpret_cast<__nv_bfloat162*>(&el[(size_t)m*DIM + n]) = lp;
                }
            }
    } else {
        float* so = g_states + base;
        __nv_bfloat16 *sh = g_sh + base, *sl = g_sl + base;
        const __nv_bfloat16* enh = g_eh + (size_t)(k+1)*MD;
        const __nv_bfloat16* enl = g_el + (size_t)(k+1)*MD;
        const bool he = (k < L_-1);
        #pragma unroll
        for (int i=0;i<4;i++)
            #pragma unroll
            for (int j=0;j<8;j++){
                const int n = nb + j*8 + c0;
                #pragma unroll
                for (int h=0;h<2;h++){
                    const int m = mb + i*16 + r0 + h*8;
                    float2 sv = *reinterpret_cast<const float2*>(&so[(size_t)m*DIM + n]);
                    float evx = 0.f, evy = 0.f;
                    if (he){
                        __nv_bfloat162 e1 = *reinterpret_cast<const __nv_bfloat162*>(&enh[(size_t)m*DIM + n]);
                        __nv_bfloat162 e2 = *reinterpret_cast<const __nv_bfloat162*>(&enl[(size_t)m*DIM + n]);
                        evx = __bfloat162float(e1.x) + __bfloat162float(e2.x);
                        evy = __bfloat162float(e1.y) + __bfloat162float(e2.y);
                    }
                    float nx = sv.x + LR*acc[i][j][h*2]   - LR*evx;
                    float ny = sv.y + LR*acc[i][j][h*2+1] - LR*evy;
                    float2 ov; ov.x = nx; ov.y = ny;
                    *reinterpret_cast<float2*>(&so[(size_t)m*DIM + n]) = ov;
                    __nv_bfloat16 hx = __float2bfloat16(nx), hy = __float2bfloat16(ny);
                    __nv_bfloat162 hp; hp.x = hx; hp.y = hy;
                    __nv_bfloat162 lp;
                    lp.x = __float2bfloat16(nx - __bfloat162float(hx));
                    lp.y = __float2bfloat16(ny - __bfloat162float(hy));
                    *reinterpret_cast<__nv_bfloat162*>(&sh[(size_t)m*DIM + n]) = hp;
                    *reinterpret_cast<__nv_bfloat162*>(&sl[(size_t)m*DIM + n]) = lp;
                }
            }
    }
}

// ---- CE: 128x128 bf16-hi logits tile + online softmax partials ----
__global__ __launch_bounds__(256,1)
void mm_ce(const int* __restrict__ targets, const float* __restrict__ oB){
    extern __shared__ char smem[];
    const uint32_t sb = smem_u32(smem);
    float* ls   = reinterpret_cast<float*>(smem + 61440);
    float* s_ob = reinterpret_cast<float*>(smem + 127488);
    int* s_ro   = reinterpret_cast<int*>(smem + 128000);
    int* s_tg   = reinterpret_cast<int*>(smem + 128512);
    const int tid = threadIdx.x;
    const int split = blockIdx.x, m0 = blockIdx.y*128, n0 = split*128;

    if (tid < 128){
        int rg = m0 + tid;
        if (rg < NROWS){
            int b = rg/(S_-1), s = rg%(S_-1);
            s_ro[tid] = (b*S_ + s)*DIM;
            s_tg[tid] = targets[b*S_ + s + 1];
        } else { s_ro[tid] = 0; s_tg[tid] = -1; }
        s_ob[tid] = oB[n0 + tid];
    }
    __syncthreads();

    const __nv_bfloat16* A3 = g_sh + (size_t)3*MD;
    const __nv_bfloat16* Bw = g_oWh + (size_t)n0*DIM;

    auto issue = [&](int kt){
        const uint32_t st = sb + (uint32_t)(kt%3)*20480u;
        const int k0 = kt*32;
        #pragma unroll
        for (int it = 0; it < 2; it++){
            int c = it*256 + tid, row = c>>2, cc = c&3;
            CP16(st + row*80 + cc*16, A3 + s_ro[row] + k0 + cc*8);
            CP16(st + 10240 + row*80 + cc*16, Bw + (size_t)row*DIM + k0 + cc*8);
        }
        CP_COMMIT();
    };

    const int w = tid>>5, l = tid&31;
    const int wm = w>>2, wn = w&3;
    const int aoff = wm*64, boff = wn*32;
    const uint32_t apart = (uint32_t)((aoff + ((l>>3)&1)*8 + (l&7))*80 + (l>>4)*16);
    const uint32_t bpart = (uint32_t)((boff + (l>>4)*8 + (l&7))*80 + ((l>>3)&1)*16);

    float acc[4][4][4];
    #pragma unroll
    for (int i=0;i<4;i++)
        #pragma unroll
        for (int j=0;j<4;j++)
            #pragma unroll
            for (int q=0;q<4;q++) acc[i][j][q] = 0.f;

    issue(0); issue(1);
    for (int kt = 0; kt < 32; kt++){
        if (kt == 31) CP_WAIT0(); else CP_WAIT1();
        __syncthreads();
        if (kt + 2 < 32) issue(kt + 2);
        const uint32_t st = sb + (uint32_t)(kt%3)*20480u;
        #pragma unroll
        for (int ks = 0; ks < 2; ks++){
            uint32_t ah[4][4], bh[4][2];
            #pragma unroll
            for (int i=0;i<4;i++){
                uint32_t ad = st + apart + i*1280 + ks*32;
                LDSM4(ah[i][0],ah[i][1],ah[i][2],ah[i][3], ad);
            }
            #pragma unroll
            for (int jp=0;jp<2;jp++){
                uint32_t bd = st + 10240 + bpart + jp*1280 + ks*32;
                LDSM4(bh[2*jp][0],bh[2*jp][1],bh[2*jp+1][0],bh[2*jp+1][1], bd);
            }
            #pragma unroll
            for (int i=0;i<4;i++)
                #pragma unroll
                for (int j=0;j<4;j++)
                    MMA(acc[i][j], ah[i], bh[j]);
        }
    }

    const int r0 = l>>2, c0 = (l&3)*2;
    #pragma unroll
    for (int i=0;i<4;i++)
        #pragma unroll
        for (int j=0;j<4;j++)
            #pragma unroll
            for (int h=0;h<2;h++){
                int rr = aoff + i*16 + r0 + h*8;
                int cc = boff + j*8 + c0;
                ls[rr*129 + cc]     = acc[i][j][h*2];
                ls[rr*129 + cc + 1] = acc[i][j][h*2+1];
            }
    __syncthreads();

    if (tid < 128){
        const int r = m0 + tid, tg = s_tg[tid];
        float mx = -1e30f;
        #pragma unroll 8
        for (int c = 0; c < 128; c++){
            float v = ls[tid*129 + c] + s_ob[c];
            mx = fmaxf(mx, v);
        }
        float sm = 0.f, tl = -1e30f;
        #pragma unroll 8
        for (int c = 0; c < 128; c++){
            float v = ls[tid*129 + c] + s_ob[c];
            sm += __expf(v - mx);
            if (n0 + c == tg) tl = v;
        }
        if (r < NROWS){
            g_pm[r*NSP + split] = mx;
            g_ps[r*NSP + split] = sm;
            g_pt[r*NSP + split] = tl;
        }
    }
}

// ---- reductions ----
__global__ void pc_reduce_kernel(){
    __shared__ double sm[256];
    double local = 0.0;
    const uint4* H = reinterpret_cast<const uint4*>(g_eh);
    const uint4* Lo = reinterpret_cast<const uint4*>(g_el);
    for (int i = blockIdx.x*blockDim.x + threadIdx.x; i < LMD/8; i += gridDim.x*blockDim.x){
        uint4 hv = H[i], lv = Lo[i];
        const __nv_bfloat162* hp = reinterpret_cast<const __nv_bfloat162*>(&hv);
        const __nv_bfloat162* lp = reinterpret_cast<const __nv_bfloat162*>(&lv);
        #pragma unroll
        for (int q = 0; q < 4; q++){
            float ex = __bfloat162float(hp[q].x) + __bfloat162float(lp[q].x);
            float ey = __bfloat162float(hp[q].y) + __bfloat162float(lp[q].y);
            local += (double)ex*ex + (double)ey*ey;
        }
    }
    sm[threadIdx.x] = local; __syncthreads();
    for (int s = 128; s > 0; s >>= 1){
        if (threadIdx.x < s) sm[threadIdx.x] += sm[threadIdx.x + s];
        __syncthreads();
    }
    if (threadIdx.x == 0) g_pc_part[blockIdx.x] = sm[0];
}
__global__ void ce_combine_kernel(){
    __shared__ double sm[256];
    double local = 0.0;
    for (int r = blockIdx.x*blockDim.x + threadIdx.x; r < NROWS; r += gridDim.x*blockDim.x){
        float M = -1e30f;
        for (int sp = 0; sp < NSP; sp++) M = fmaxf(M, g_pm[r*NSP + sp]);
        float Z = 0.f;
        for (int sp = 0; sp < NSP; sp++) Z += g_ps[r*NSP + sp]*__expf(g_pm[r*NSP + sp] - M);
        float tl = -1e30f;
        for (int sp = 0; sp < NSP; sp++) tl = fmaxf(tl, g_pt[r*NSP + sp]);
        local += (double)M + log((double)Z) - (double)tl;
    }
    sm[threadIdx.x] = local; __syncthreads();
    for (int s = 128; s > 0; s >>= 1){
        if (threadIdx.x < s) sm[threadIdx.x] += sm[threadIdx.x + s];
        __syncthreads();
    }
    if (threadIdx.x == 0) g_ce_part[blockIdx.x] = sm[0];
}
__global__ void finalize_kernel(float* out){
    double pc = 0.0, ce = 0.0;
    for (int i = 0; i < NPCB; i++) pc += g_pc_part[i];
    for (int i = 0; i < NCEB; i++) ce += g_ce_part[i];
    out[0] = (float)(ce/(double)NROWS);
    out[1] = (float)(pc/(double)LMD);
}

// ---- launch ----
extern "C" void kernel_launch(void* const* d_in, const int* in_sizes, int n_in,
                              void* d_out, int out_size){
    const int*   input_ids   = (const int*)d_in[0];
    const int*   targets     = (const int*)d_in[1];
    const float* emb         = (const float*)d_in[2];
    const float* W_stack     = (const float*)d_in[3];
    const float* b_stack     = (const float*)d_in[4];
    const float* out_W       = (const float*)d_in[5];
    const float* out_b       = (const float*)d_in[6];
    const float* states_init = (const float*)d_in[7];
    float* out = (float*)d_out;

    constexpr int GSMEM = 3*61440;     // 180 KB
    constexpr int CSMEM = 129024;      // ~126 KB
    cudaFuncSetAttribute(mm_step<0>, cudaFuncAttributeMaxDynamicSharedMemorySize, GSMEM);
    cudaFuncSetAttribute(mm_step<1>, cudaFuncAttributeMaxDynamicSharedMemorySize, GSMEM);
    cudaFuncSetAttribute(mm_ce,      cudaFuncAttributeMaxDynamicSharedMemorySize, CSMEM);

    split_states_kernel<<<LMD/1024, 256>>>(states_init);
    gather_kernel<<<M_, 256>>>(input_ids, emb);
    split_w_kernel<<<dim3(32,32,L_), dim3(32,8)>>>(W_stack);
    split_ow_kernel<<<(V_*DIM)/1024, 256>>>(out_W);

    dim3 gg(DIM/256, M_/128, L_);   // (4, 32, 4) = 512 blocks, layers fused
    for (int step = 0; step < STEPS; step++){
        mm_step<0><<<gg, 256, GSMEM>>>(b_stack);
        mm_step<1><<<gg, 256, GSMEM>>>(b_stack);
    }
    mm_step<0><<<gg, 256, GSMEM>>>(b_stack);

    pc_reduce_kernel<<<NPCB, 256>>>();
    mm_ce<<<dim3(NSP, M_/128), 256, CSMEM>>>(targets, out_b);
    ce_combine_kernel<<<NCEB, 256>>>();
    finalize_kernel<<<1, 1>>>(out);
}